// round 12
// baseline (speedup 1.0000x reference)
#include <cuda_runtime.h>
#include <math.h>
#include <stdint.h>

// Problem constants (fixed by the reference setup_inputs).
#define BB       64
#define SS       2048
#define HH       1024
#define H4       (HH / 4)          // 256 float4 per enc row
#define SPLITS   16
#define CHUNK    (SS / SPLITS)     // 128 seq rows per CTA
#define NT       256
#define NW       (NT / 32)         // 8 warps
#define NIT      (CHUNK / NW)      // 16 rows per warp
#define NSTG     3                 // per-warp ring depth
#define ROW_BYTES (HH * 4)         // 4 KB per enc row

// Dynamic smem layout (bytes). Slots: warp w, slot s at (w*NSTG + s)*4KB.
#define OFF_SLOTS 0
#define SLOTS_BYTES (NW * NSTG * ROW_BYTES)    // 96 KB
#define OFF_MBAR  SLOTS_BYTES                  // 24 mbarriers x 8 B
#define OFF_M     (OFF_MBAR + NW * NSTG * 8)
#define OFF_L     (OFF_M + 64)
#define OFF_LAST  (OFF_L + 64)
#define OFF_SCORE (OFF_LAST + 64)
#define SMEM_SZ   (OFF_SCORE + CHUNK * 4 + 128)

// Scratch for split-K partials (static device globals: no allocation allowed).
__device__ float g_pm[BB * SPLITS];
__device__ float g_pl[BB * SPLITS];
__device__ float g_pctx[(size_t)BB * SPLITS * HH];   // 4 MB
__device__ unsigned int g_cnt[BB];                    // arrival counters (self-resetting)

__device__ __forceinline__ uint32_t smem_u32(const void* p) {
    uint32_t a;
    asm("{ .reg .u64 t; cvta.to.shared.u64 t, %1; cvt.u32.u64 %0, t; }" : "=r"(a) : "l"(p));
    return a;
}
__device__ __forceinline__ void mbar_init(uint32_t mbar, uint32_t cnt) {
    asm volatile("mbarrier.init.shared.b64 [%0], %1;" :: "r"(mbar), "r"(cnt) : "memory");
}
__device__ __forceinline__ void mbar_expect_tx(uint32_t mbar, uint32_t bytes) {
    asm volatile("mbarrier.arrive.expect_tx.shared.b64 _, [%0], %1;" :: "r"(mbar), "r"(bytes) : "memory");
}
__device__ __forceinline__ void bulk_g2s(uint32_t dst, const void* src, uint32_t bytes, uint32_t mbar) {
    asm volatile("cp.async.bulk.shared::cluster.global.mbarrier::complete_tx::bytes [%0], [%1], %2, [%3];"
                 :: "r"(dst), "l"(src), "r"(bytes), "r"(mbar) : "memory");
}
__device__ __forceinline__ void mbar_wait(uint32_t mbar, uint32_t parity) {
    uint32_t done;
    asm volatile("{\n\t.reg .pred p;\n\t"
                 "mbarrier.try_wait.parity.acquire.cta.shared::cta.b64 p, [%1], %2;\n\t"
                 "selp.b32 %0, 1, 0, p;\n\t}"
                 : "=r"(done) : "r"(mbar), "r"(parity) : "memory");
    if (!done) {
        asm volatile("{\n\t.reg .pred P1;\n\t"
                     "W%=:\n\t"
                     "mbarrier.try_wait.parity.acquire.cta.shared::cta.b64 P1, [%0], %1, 0x989680;\n\t"
                     "@P1 bra.uni D%=;\n\t"
                     "bra.uni W%=;\n\t"
                     "D%=:\n\t}"
                     :: "r"(mbar), "r"(parity) : "memory");
    }
}

// -----------------------------------------------------------------------------
// Single fused kernel. grid = BB*SPLITS = 1024, block = NT.
// Each warp runs a PRIVATE TMA pipeline: its own 3-slot x 4KB ring + 3
// mbarriers; lane 0 issues cp.async.bulk refills for its own rows
// (row = it*8 + w, so the 8 warps' in-flight rows stay contiguous in DRAM).
// No __syncthreads and no cross-warp coupling anywhere in the mainloop.
// Tail: CTA combine + last-CTA-per-batch epilogue (context + weights).
// -----------------------------------------------------------------------------
__global__ __launch_bounds__(NT, 2) void luong_fused(
    const float* __restrict__ dec_h,
    const float* __restrict__ dec_c,
    const float* __restrict__ enc,
    float* __restrict__ ctx_out,
    float* __restrict__ weights_io)
{
    extern __shared__ __align__(128) char smem[];
    const int b     = blockIdx.x / SPLITS;
    const int split = blockIdx.x % SPLITS;
    const int t     = threadIdx.x;
    const int lane  = t & 31;
    const int w     = t >> 5;

    const uint32_t smem_base = smem_u32(smem);
    const uint32_t my_slot0  = smem_base + OFF_SLOTS + (uint32_t)(w * NSTG) * ROW_BYTES;
    const uint32_t my_mbar0  = smem_base + OFF_MBAR + (uint32_t)(w * NSTG) * 8;
    float* sm_m      = (float*)(smem + OFF_M);
    float* sm_l      = (float*)(smem + OFF_L);
    int*   sm_last   = (int*)(smem + OFF_LAST);
    float* sm_scores = (float*)(smem + OFF_SCORE);

    // Per-warp pipeline init + prologue: lane 0 inits ITS OWN mbarriers and
    // issues the first NSTG row loads. Only warp-local visibility needed.
    const char* gsrc = (const char*)(enc + (size_t)b * SS * HH + (size_t)split * CHUNK * HH);
    if (lane == 0) {
        #pragma unroll
        for (int i = 0; i < NSTG; ++i) mbar_init(my_mbar0 + i * 8, 1);
        asm volatile("fence.proxy.async.shared::cta;" ::: "memory");
        #pragma unroll
        for (int i = 0; i < NSTG; ++i) {
            mbar_expect_tx(my_mbar0 + i * 8, ROW_BYTES);
            bulk_g2s(my_slot0 + i * ROW_BYTES,
                     gsrc + (size_t)(i * NW + w) * ROW_BYTES, ROW_BYTES, my_mbar0 + i * 8);
        }
    }
    __syncwarp();

    // dec slice replicated per warp: lane holds float4 cols {j*32+lane}.
    float4 d[8];
    {
        const float4* hp = (const float4*)(dec_h + (size_t)b * HH);
        const float4* cp = (const float4*)(dec_c + (size_t)b * HH);
        #pragma unroll
        for (int j = 0; j < 8; ++j) {
            float4 a = hp[j * 32 + lane], c = cp[j * 32 + lane];
            d[j] = make_float4(a.x + c.x, a.y + c.y, a.z + c.z, a.w + c.w);
        }
    }

    float  m = -INFINITY;
    float  l = 0.0f;
    float4 acc[8];
    #pragma unroll
    for (int j = 0; j < 8; ++j) acc[j] = make_float4(0.f, 0.f, 0.f, 0.f);

    int slot = 0, parity = 0;
    for (int it = 0; it < NIT; ++it) {
        mbar_wait(my_mbar0 + slot * 8, parity);

        const float4* rp = (const float4*)(smem + OFF_SLOTS + (size_t)(w * NSTG + slot) * ROW_BYTES);
        float4 e[8];
        #pragma unroll
        for (int j = 0; j < 8; ++j) e[j] = rp[j * 32 + lane];

        float p = 0.f;
        #pragma unroll
        for (int j = 0; j < 8; ++j)
            p += e[j].x * d[j].x + e[j].y * d[j].y + e[j].z * d[j].z + e[j].w * d[j].w;
        #pragma unroll
        for (int o = 16; o > 0; o >>= 1)
            p += __shfl_xor_sync(0xffffffffu, p, o);

        // Refill this slot for row (it+NSTG)*8 + w. Warp-wide LDS above have
        // already read the banks by the time TMA data can land (>=400cyc away).
        if (lane == 0 && it + NSTG < NIT) {
            mbar_expect_tx(my_mbar0 + slot * 8, ROW_BYTES);
            bulk_g2s(my_slot0 + slot * ROW_BYTES,
                     gsrc + (size_t)((it + NSTG) * NW + w) * ROW_BYTES, ROW_BYTES,
                     my_mbar0 + slot * 8);
        }

        if (lane == 0) sm_scores[it * NW + w] = p;

        // Online softmax (warp-uniform rescale, rare after warmup).
        if (p > m) {
            const float scale = __expf(m - p);
            l *= scale;
            #pragma unroll
            for (int j = 0; j < 8; ++j) {
                acc[j].x *= scale; acc[j].y *= scale;
                acc[j].z *= scale; acc[j].w *= scale;
            }
            m = p;
        }
        const float pe = __expf(p - m);
        l += pe;
        #pragma unroll
        for (int j = 0; j < 8; ++j) {
            acc[j].x += pe * e[j].x;
            acc[j].y += pe * e[j].y;
            acc[j].z += pe * e[j].z;
            acc[j].w += pe * e[j].w;
        }

        if (++slot == NSTG) { slot = 0; parity ^= 1; }
    }

    // ---- CTA combine across the 8 warps (slot buffer reused as scratch) ----
    if (lane == 0) { sm_m[w] = m; sm_l[w] = l; }
    __syncthreads();

    float gm = sm_m[0];
    #pragma unroll
    for (int i = 1; i < NW; ++i) gm = fmaxf(gm, sm_m[i]);
    float gl = 0.f;
    #pragma unroll
    for (int i = 0; i < NW; ++i) gl += sm_l[i] * __expf(sm_m[i] - gm);

    float4* sm_acc = (float4*)(smem + OFF_SLOTS);   // 32 KB scratch
    const float ws = __expf(m - gm);
    #pragma unroll
    for (int j = 0; j < 8; ++j) {
        float4 a = acc[j];
        a.x *= ws; a.y *= ws; a.z *= ws; a.w *= ws;
        sm_acc[w * H4 + j * 32 + lane] = a;
    }
    __syncthreads();

    float4 s = make_float4(0.f, 0.f, 0.f, 0.f);
    #pragma unroll
    for (int i = 0; i < NW; ++i) {
        float4 a = sm_acc[i * H4 + t];
        s.x += a.x; s.y += a.y; s.z += a.z; s.w += a.w;
    }
    ((float4*)g_pctx)[(size_t)blockIdx.x * H4 + t] = s;
    if (t == 0) { g_pm[blockIdx.x] = gm; g_pl[blockIdx.x] = gl; }

    // Raw-score stash (threads 0..CHUNK-1, coalesced).
    if (t < CHUNK)
        weights_io[(size_t)b * SS + split * CHUNK + t] = sm_scores[t];

    // ---- Last-CTA-per-batch combine (replaces a second kernel) ----
    __threadfence();                 // make partials + raw scores visible
    __syncthreads();                 // all threads' writes precede the fence use
    if (t == 0) {
        unsigned int prev = atomicAdd(&g_cnt[b], 1u);
        sm_last[0] = (prev == SPLITS - 1);
    }
    __syncthreads();
    if (!sm_last[0]) return;

    // This CTA is the last of batch b: all splits' partials are visible.
    float M = -INFINITY;
    #pragma unroll
    for (int i = 0; i < SPLITS; ++i)
        M = fmaxf(M, g_pm[b * SPLITS + i]);
    float L = 0.f;
    #pragma unroll
    for (int i = 0; i < SPLITS; ++i)
        L += g_pl[b * SPLITS + i] * __expf(g_pm[b * SPLITS + i] - M);
    const float invl = 1.0f / L;

    // Context: thread t combines column t across the splits (L2-hot).
    float4 cs = make_float4(0.f, 0.f, 0.f, 0.f);
    #pragma unroll
    for (int i = 0; i < SPLITS; ++i) {
        const float wv = __expf(g_pm[b * SPLITS + i] - M);
        float4 p = ((const float4*)g_pctx)[(size_t)(b * SPLITS + i) * H4 + t];
        cs.x += wv * p.x; cs.y += wv * p.y; cs.z += wv * p.z; cs.w += wv * p.w;
    }
    cs.x *= invl; cs.y *= invl; cs.z *= invl; cs.w *= invl;
    ((float4*)ctx_out)[(size_t)b * H4 + t] = cs;

    // Weights finalize in-place: raw score -> exp(s - M) / L (8 per thread).
    #pragma unroll
    for (int k = 0; k < SS / NT; ++k) {
        const size_t idx = (size_t)b * SS + k * NT + t;
        weights_io[idx] = __expf(weights_io[idx] - M) * invl;
    }

    // Reset the counter for the next graph replay (deterministic).
    if (t == 0) g_cnt[b] = 0u;
}

// -----------------------------------------------------------------------------
// Harness entry. Inputs (metadata order): dec_state_h [B,H] f32,
// dec_state_c [B,H] f32, enc_output [B,S,H] f32.
// Output: concat(context_vector [B,H], attention_weights [B,S,1]) f32.
// -----------------------------------------------------------------------------
extern "C" void kernel_launch(void* const* d_in, const int* in_sizes, int n_in,
                              void* d_out, int out_size)
{
    (void)in_sizes; (void)n_in; (void)out_size;
    const float* dec_h = (const float*)d_in[0];
    const float* dec_c = (const float*)d_in[1];
    const float* enc   = (const float*)d_in[2];
    float* out = (float*)d_out;
    float* ctx = out;                       // [B, H]
    float* wts = out + (size_t)BB * HH;     // [B, S, 1]

    // Unconditional (no static guards): idempotent attribute set, capture-safe.
    cudaFuncSetAttribute(luong_fused, cudaFuncAttributeMaxDynamicSharedMemorySize, SMEM_SZ);

    luong_fused<<<BB * SPLITS, NT, SMEM_SZ>>>(dec_h, dec_c, enc, ctx, wts);
}

// round 13
// speedup vs baseline: 1.0143x; 1.0143x over previous
#include <cuda_runtime.h>
#include <math.h>
#include <stdint.h>

// Problem constants (fixed by the reference setup_inputs).
#define BB       64
#define SS       2048
#define HH       1024
#define H4       (HH / 4)          // 256 float4 per enc row
#define SPLITS   16
#define CHUNK    (SS / SPLITS)     // 128 seq rows per CTA
#define NT       256
#define NW       (NT / 32)         // 8 warps
#define STG_ROWS 8                 // rows per pipeline stage (one per warp)
#define NSTG     3                 // triple buffer
#define NIT      (CHUNK / STG_ROWS)        // 16 stages per CTA
#define STG_BYTES (STG_ROWS * HH * 4)      // 32 KB

// Dynamic smem layout (bytes).
#define OFF_STAGE 0
#define OFF_MBAR  (NSTG * STG_BYTES)           // 3 x 8B mbarriers
#define OFF_M     (OFF_MBAR + 64)
#define OFF_L     (OFF_M + 64)
#define OFF_LAST  (OFF_L + 64)
#define OFF_SCORE (OFF_LAST + 64)
#define SMEM_SZ   (OFF_SCORE + CHUNK * 4 + 128)

// Scratch for split-K partials (static device globals: no allocation allowed).
__device__ float g_pm[BB * SPLITS];
__device__ float g_pl[BB * SPLITS];
__device__ float g_pctx[(size_t)BB * SPLITS * HH];   // 4 MB
__device__ unsigned int g_cnt[BB];                    // arrival counters (self-resetting)

__device__ __forceinline__ uint32_t smem_u32(const void* p) {
    uint32_t a;
    asm("{ .reg .u64 t; cvta.to.shared.u64 t, %1; cvt.u32.u64 %0, t; }" : "=r"(a) : "l"(p));
    return a;
}
__device__ __forceinline__ void mbar_init(uint32_t mbar, uint32_t cnt) {
    asm volatile("mbarrier.init.shared.b64 [%0], %1;" :: "r"(mbar), "r"(cnt) : "memory");
}
__device__ __forceinline__ void mbar_expect_tx(uint32_t mbar, uint32_t bytes) {
    asm volatile("mbarrier.arrive.expect_tx.shared.b64 _, [%0], %1;" :: "r"(mbar), "r"(bytes) : "memory");
}
__device__ __forceinline__ uint64_t mk_evict_first_policy() {
    uint64_t pol;
    asm("createpolicy.fractional.L2::evict_first.b64 %0, 1.0;" : "=l"(pol));
    return pol;
}
// Bulk copy with L2 evict-first hint: enc is a zero-reuse stream; keep the hot
// set (pctx partials, scores, dec) resident in L2 instead.
__device__ __forceinline__ void bulk_g2s(uint32_t dst, const void* src, uint32_t bytes,
                                         uint32_t mbar, uint64_t pol) {
    asm volatile("cp.async.bulk.shared::cluster.global.mbarrier::complete_tx::bytes.L2::cache_hint"
                 " [%0], [%1], %2, [%3], %4;"
                 :: "r"(dst), "l"(src), "r"(bytes), "r"(mbar), "l"(pol) : "memory");
}
__device__ __forceinline__ void mbar_wait(uint32_t mbar, uint32_t parity) {
    uint32_t done;
    asm volatile("{\n\t.reg .pred p;\n\t"
                 "mbarrier.try_wait.parity.acquire.cta.shared::cta.b64 p, [%1], %2;\n\t"
                 "selp.b32 %0, 1, 0, p;\n\t}"
                 : "=r"(done) : "r"(mbar), "r"(parity) : "memory");
    if (!done) {
        asm volatile("{\n\t.reg .pred P1;\n\t"
                     "W%=:\n\t"
                     "mbarrier.try_wait.parity.acquire.cta.shared::cta.b64 P1, [%0], %1, 0x989680;\n\t"
                     "@P1 bra.uni D%=;\n\t"
                     "bra.uni W%=;\n\t"
                     "D%=:\n\t}"
                     :: "r"(mbar), "r"(parity) : "memory");
    }
}

// -----------------------------------------------------------------------------
// Single fused kernel (best-measured R8 structure). grid = BB*SPLITS = 1024.
// Main loop: cp.async.bulk triple-buffered pipeline (evict-first L2 hint)
// feeding warp-per-row online softmax; dec + accumulators in registers.
// Tail: last CTA per batch combines split partials, writes context and
// finalizes attention weights in-place.
// -----------------------------------------------------------------------------
__global__ __launch_bounds__(NT, 2) void luong_fused(
    const float* __restrict__ dec_h,
    const float* __restrict__ dec_c,
    const float* __restrict__ enc,
    float* __restrict__ ctx_out,
    float* __restrict__ weights_io)
{
    extern __shared__ __align__(128) char smem[];
    const int b     = blockIdx.x / SPLITS;
    const int split = blockIdx.x % SPLITS;
    const int t     = threadIdx.x;
    const int lane  = t & 31;
    const int w     = t >> 5;

    const uint32_t smem_base = smem_u32(smem);
    const uint32_t mbar0 = smem_base + OFF_MBAR;
    float* sm_m      = (float*)(smem + OFF_M);
    float* sm_l      = (float*)(smem + OFF_L);
    int*   sm_last   = (int*)(smem + OFF_LAST);
    float* sm_scores = (float*)(smem + OFF_SCORE);

    const uint64_t pol = mk_evict_first_policy();

    // Pipeline init, then kick off the first NSTG TMA stages BEFORE touching
    // dec state, so the global stream starts immediately.
    if (t == 0) {
        #pragma unroll
        for (int i = 0; i < NSTG; ++i) mbar_init(mbar0 + i * 8, 1);
    }
    __syncthreads();
    asm volatile("fence.proxy.async.shared::cta;" ::: "memory");

    const char* gsrc = (const char*)(enc + (size_t)b * SS * HH + (size_t)split * CHUNK * HH);
    if (t == 0) {
        #pragma unroll
        for (int i = 0; i < NSTG; ++i) {
            mbar_expect_tx(mbar0 + i * 8, STG_BYTES);
            bulk_g2s(smem_base + OFF_STAGE + i * STG_BYTES,
                     gsrc + (size_t)i * STG_BYTES, STG_BYTES, mbar0 + i * 8, pol);
        }
    }

    // dec slice replicated per warp: lane holds float4 cols {j*32+lane}.
    float4 d[8];
    {
        const float4* hp = (const float4*)(dec_h + (size_t)b * HH);
        const float4* cp = (const float4*)(dec_c + (size_t)b * HH);
        #pragma unroll
        for (int j = 0; j < 8; ++j) {
            float4 a = hp[j * 32 + lane], c = cp[j * 32 + lane];
            d[j] = make_float4(a.x + c.x, a.y + c.y, a.z + c.z, a.w + c.w);
        }
    }

    float  m = -INFINITY;
    float  l = 0.0f;
    float4 acc[8];
    #pragma unroll
    for (int j = 0; j < 8; ++j) acc[j] = make_float4(0.f, 0.f, 0.f, 0.f);

    int slot = 0, parity = 0;
    for (int it = 0; it < NIT; ++it) {
        mbar_wait(mbar0 + slot * 8, parity);

        // Warp w consumes row (it*8 + w) of the chunk from smem.
        const float4* rp = (const float4*)(smem + OFF_STAGE + slot * STG_BYTES + w * (HH * 4));
        float4 e[8];
        #pragma unroll
        for (int j = 0; j < 8; ++j) e[j] = rp[j * 32 + lane];

        float p = 0.f;
        #pragma unroll
        for (int j = 0; j < 8; ++j)
            p += e[j].x * d[j].x + e[j].y * d[j].y + e[j].z * d[j].z + e[j].w * d[j].w;
        #pragma unroll
        for (int o = 16; o > 0; o >>= 1)
            p += __shfl_xor_sync(0xffffffffu, p, o);

        if (lane == 0) sm_scores[it * STG_ROWS + w] = p;

        // Online softmax (warp-uniform rescale, rare after warmup).
        if (p > m) {
            const float scale = __expf(m - p);
            l *= scale;
            #pragma unroll
            for (int j = 0; j < 8; ++j) {
                acc[j].x *= scale; acc[j].y *= scale;
                acc[j].z *= scale; acc[j].w *= scale;
            }
            m = p;
        }
        const float pe = __expf(p - m);
        l += pe;
        #pragma unroll
        for (int j = 0; j < 8; ++j) {
            acc[j].x += pe * e[j].x;
            acc[j].y += pe * e[j].y;
            acc[j].z += pe * e[j].z;
            acc[j].w += pe * e[j].w;
        }

        __syncthreads();   // everyone done with this slot
        if (t == 0 && it + NSTG < NIT) {
            mbar_expect_tx(mbar0 + slot * 8, STG_BYTES);
            bulk_g2s(smem_base + OFF_STAGE + slot * STG_BYTES,
                     gsrc + (size_t)(it + NSTG) * STG_BYTES, STG_BYTES, mbar0 + slot * 8, pol);
        }
        if (++slot == NSTG) { slot = 0; parity ^= 1; }
    }

    // ---- CTA combine across the 8 warps (stage buffer reused as scratch) ----
    if (lane == 0) { sm_m[w] = m; sm_l[w] = l; }
    __syncthreads();

    float gm = sm_m[0];
    #pragma unroll
    for (int i = 1; i < NW; ++i) gm = fmaxf(gm, sm_m[i]);
    float gl = 0.f;
    #pragma unroll
    for (int i = 0; i < NW; ++i) gl += sm_l[i] * __expf(sm_m[i] - gm);

    float4* sm_acc = (float4*)(smem + OFF_STAGE);   // 32 KB scratch
    const float ws = __expf(m - gm);
    #pragma unroll
    for (int j = 0; j < 8; ++j) {
        float4 a = acc[j];
        a.x *= ws; a.y *= ws; a.z *= ws; a.w *= ws;
        sm_acc[w * H4 + j * 32 + lane] = a;
    }
    __syncthreads();

    float4 s = make_float4(0.f, 0.f, 0.f, 0.f);
    #pragma unroll
    for (int i = 0; i < NW; ++i) {
        float4 a = sm_acc[i * H4 + t];
        s.x += a.x; s.y += a.y; s.z += a.z; s.w += a.w;
    }
    ((float4*)g_pctx)[(size_t)blockIdx.x * H4 + t] = s;
    if (t == 0) { g_pm[blockIdx.x] = gm; g_pl[blockIdx.x] = gl; }

    // Raw-score stash (threads 0..CHUNK-1, coalesced).
    if (t < CHUNK)
        weights_io[(size_t)b * SS + split * CHUNK + t] = sm_scores[t];

    // ---- Last-CTA-per-batch combine (replaces a second kernel) ----
    __threadfence();                 // make partials + raw scores visible
    __syncthreads();                 // all threads' writes precede the fence use
    if (t == 0) {
        unsigned int prev = atomicAdd(&g_cnt[b], 1u);
        sm_last[0] = (prev == SPLITS - 1);
    }
    __syncthreads();
    if (!sm_last[0]) return;

    // This CTA is the last of batch b: all splits' partials are visible.
    float M = -INFINITY;
    #pragma unroll
    for (int i = 0; i < SPLITS; ++i)
        M = fmaxf(M, g_pm[b * SPLITS + i]);
    float L = 0.f;
    #pragma unroll
    for (int i = 0; i < SPLITS; ++i)
        L += g_pl[b * SPLITS + i] * __expf(g_pm[b * SPLITS + i] - M);
    const float invl = 1.0f / L;

    // Context: thread t combines column t across the splits (L2-hot).
    float4 cs = make_float4(0.f, 0.f, 0.f, 0.f);
    #pragma unroll
    for (int i = 0; i < SPLITS; ++i) {
        const float wv = __expf(g_pm[b * SPLITS + i] - M);
        float4 p = ((const float4*)g_pctx)[(size_t)(b * SPLITS + i) * H4 + t];
        cs.x += wv * p.x; cs.y += wv * p.y; cs.z += wv * p.z; cs.w += wv * p.w;
    }
    cs.x *= invl; cs.y *= invl; cs.z *= invl; cs.w *= invl;
    ((float4*)ctx_out)[(size_t)b * H4 + t] = cs;

    // Weights finalize in-place: raw score -> exp(s - M) / L (8 per thread).
    #pragma unroll
    for (int k = 0; k < SS / NT; ++k) {
        const size_t idx = (size_t)b * SS + k * NT + t;
        weights_io[idx] = __expf(weights_io[idx] - M) * invl;
    }

    // Reset the counter for the next graph replay (deterministic).
    if (t == 0) g_cnt[b] = 0u;
}

// -----------------------------------------------------------------------------
// Harness entry. Inputs (metadata order): dec_state_h [B,H] f32,
// dec_state_c [B,H] f32, enc_output [B,S,H] f32.
// Output: concat(context_vector [B,H], attention_weights [B,S,1]) f32.
// -----------------------------------------------------------------------------
extern "C" void kernel_launch(void* const* d_in, const int* in_sizes, int n_in,
                              void* d_out, int out_size)
{
    (void)in_sizes; (void)n_in; (void)out_size;
    const float* dec_h = (const float*)d_in[0];
    const float* dec_c = (const float*)d_in[1];
    const float* enc   = (const float*)d_in[2];
    float* out = (float*)d_out;
    float* ctx = out;                       // [B, H]
    float* wts = out + (size_t)BB * HH;     // [B, S, 1]

    // Unconditional (no static guards): idempotent attribute set, capture-safe.
    cudaFuncSetAttribute(luong_fused, cudaFuncAttributeMaxDynamicSharedMemorySize, SMEM_SZ);

    luong_fused<<<BB * SPLITS, NT, SMEM_SZ>>>(dec_h, dec_c, enc, ctx, wts);
}